// round 3
// baseline (speedup 1.0000x reference)
#include <cuda_runtime.h>
#include <cuda_bf16.h>
#include <cstdint>

// ---------------------------------------------------------------------------
// ConvKanModel: 2x [ base_conv(silu(x)) + spline_conv(bspline_bases(x)) ->
//                    instance_norm -> prelu ], then sigmoid.
// x: (4,16,512,512) f32.  Cubic B-spline on uniform grid -> closed form:
// cell = floor((x+1.75)*4); 4 nonzero bases with standard cubic weights.
// This round: inner conv loop uses packed fma.rn.f32x2 (2 lane-FMA/inst,
// 128 lane-FMA/cyc/SM vs 64 scalar) pairing adjacent output channels.
// ---------------------------------------------------------------------------

#define NB      4
#define CCH     16
#define KB      11          // number of stored bases
#define JF      12          // features per channel: silu + 11 bases
#define HW      512
#define PLANE   (HW*HW)     // 262144
#define TOTAL   (NB*CCH*PLANE)

#define TILE    32
#define HALO    (TILE+2)        // 34
#define HALO2   (HALO*HALO)     // 1156
#define NW      (JF*3*3*CCH)    // 1728 combined weights per input channel
#define SMEM_BYTES ((JF*HALO2 + NW) * 4)   // 62400 B

// Scratch (static device globals; no runtime allocation)
__device__ float g_z1[TOTAL];
__device__ float g_z2[TOTAL];
__device__ float g_m1[NB*CCH];
__device__ float g_r1[NB*CCH];
__device__ float g_m2[NB*CCH];
__device__ float g_r2[NB*CCH];

// ---- packed fp32x2 helpers (sm_103a packed pipe; ptxas won't auto-emit) ----
__device__ __forceinline__ unsigned long long pack2(float x) {
    unsigned long long r;
    asm("mov.b64 %0, {%1, %1};" : "=l"(r) : "f"(x));
    return r;
}
__device__ __forceinline__ void fma2(unsigned long long& d,
                                     unsigned long long a,
                                     unsigned long long b) {
    asm("fma.rn.f32x2 %0, %1, %2, %0;" : "+l"(d) : "l"(a), "l"(b));
}

// ---------------------------------------------------------------------------
// Fused KAN conv. Block: 256 threads, 32x32 pixel tile, all 16 out channels.
// Thread: 8 pixels (one column, 8 consecutive rows) x 8 out channels
// (4 packed f32x2 accumulator pairs).
// ---------------------------------------------------------------------------
template<bool NORM>
__global__ __launch_bounds__(256, 2)
void conv_kan_kernel(const float* __restrict__ in,
                     const float* __restrict__ base_w,    // [16][16][3][3]
                     const float* __restrict__ spline_w,  // [16][176][3][3]
                     const float* __restrict__ mean,
                     const float* __restrict__ rstd,
                     const float* __restrict__ alpha_p,
                     float* __restrict__ out)
{
    extern __shared__ float smem[];
    float* s_act = smem;                 // [JF][HALO2]
    float* s_w   = smem + JF*HALO2;      // [JF][3][3][16]  (16 = outch, contiguous)

    const int tid    = threadIdx.x;
    const int col    = tid & 31;         // 0..31  (x within tile)
    const int rowgrp = (tid >> 5) & 3;   // 0..3   (8-row group)
    const int ohalf  = tid >> 7;         // 0..1   (out-channel half)
    const int bx     = blockIdx.x * TILE;
    const int by     = blockIdx.y * TILE;
    const int b      = blockIdx.z;

    const float alpha = NORM ? alpha_p[0] : 0.0f;

    // 8 rows x 4 outch-pairs of packed f32x2 accumulators
    unsigned long long acc[8][4];
#pragma unroll
    for (int r = 0; r < 8; ++r)
#pragma unroll
        for (int p = 0; p < 4; ++p) acc[r][p] = 0ull;

    for (int c = 0; c < CCH; ++c) {
        __syncthreads();   // protect previous iteration's reads

        // ---- build activation tile for input channel c ----
        const float* inp = in + ((size_t)(b*CCH + c)) * PLANE;
        float mu = 0.0f, rs = 0.0f;
        if (NORM) { mu = mean[b*CCH + c]; rs = rstd[b*CCH + c]; }

        for (int idx = tid; idx < HALO2; idx += 256) {
            const int iy = idx / HALO;
            const int ix = idx - iy * HALO;
            const int gy = by + iy - 1;
            const int gx = bx + ix - 1;

            float a0 = 0.0f, w0 = 0.0f, w1 = 0.0f, w2 = 0.0f, w3 = 0.0f;
            int cell = -100;
            if (gy >= 0 && gy < HW && gx >= 0 && gx < HW) {
                float x = inp[gy*HW + gx];
                if (NORM) {
                    x = (x - mu) * rs;
                    x = (x < 0.0f) ? alpha * x : x;   // prelu
                }
                a0 = x / (1.0f + __expf(-x));          // silu
                const float u  = (x + 1.75f) * 4.0f;
                const float cf = floorf(u);
                const int ci = (int)cf;
                if (ci >= 0 && ci < 14) {
                    cell = ci;
                    const float t  = u - cf;
                    const float mt = 1.0f - t;
                    const float t2 = t*t, t3 = t2*t;
                    w0 = mt*mt*mt * (1.0f/6.0f);
                    w1 = (3.0f*t3 - 6.0f*t2 + 4.0f) * (1.0f/6.0f);
                    w2 = (-3.0f*t3 + 3.0f*t2 + 3.0f*t + 1.0f) * (1.0f/6.0f);
                    w3 = t3 * (1.0f/6.0f);
                }
            }
            s_act[idx] = a0;                     // feature 0 = silu
#pragma unroll
            for (int j = 1; j < JF; ++j) s_act[j*HALO2 + idx] = 0.0f;
            if (cell >= 0) {
                // nonzero stored bases are (cell-3..cell) clipped to 0..10,
                // living in feature slots j = basis+1
                if (cell >= 3)               s_act[(cell-2)*HALO2 + idx] = w0;
                if (cell >= 2 && cell <= 12) s_act[(cell-1)*HALO2 + idx] = w1;
                if (cell >= 1 && cell <= 11) s_act[(cell  )*HALO2 + idx] = w2;
                if (cell <= 10)              s_act[(cell+1)*HALO2 + idx] = w3;
            }
        }

        // ---- load combined weights for channel c: [j][ky][kx][o] ----
        for (int idx = tid; idx < NW; idx += 256) {
            const int o    = idx & 15;
            const int rest = idx >> 4;        // 0..107
            const int kx   = rest % 3;
            const int ky   = (rest / 3) % 3;
            const int j    = rest / 9;        // 0..11
            float w;
            if (j == 0) w = base_w[((o*CCH + c)*3 + ky)*3 + kx];
            else        w = spline_w[((o*(CCH*KB) + (c*KB + j - 1))*3 + ky)*3 + kx];
            s_w[((j*3 + ky)*3 + kx)*CCH + o] = w;
        }
        __syncthreads();

        // ---- accumulate: 12 features x 9 taps, packed f32x2 ----
        const int rbase = rowgrp * 8;
        for (int j = 0; j < JF; ++j) {
            const float* actj = s_act + j*HALO2;
            const float* wj   = s_w + j*9*CCH + ohalf*8;
#pragma unroll
            for (int ky = 0; ky < 3; ++ky) {
#pragma unroll
                for (int kx = 0; kx < 3; ++kx) {
                    // 4 outch-pairs as one aligned LDS.64 each (broadcast per warp)
                    const unsigned long long* wp =
                        reinterpret_cast<const unsigned long long*>(wj + (ky*3 + kx)*CCH);
                    unsigned long long wv[4];
#pragma unroll
                    for (int p = 0; p < 4; ++p) wv[p] = wp[p];
#pragma unroll
                    for (int r = 0; r < 8; ++r) {
                        const float av = actj[(rbase + r + ky)*HALO + col + kx];
                        const unsigned long long a2 = pack2(av);
#pragma unroll
                        for (int p = 0; p < 4; ++p)
                            fma2(acc[r][p], a2, wv[p]);
                    }
                }
            }
        }
    }

    // ---- epilogue: unpack & write 8 pixels x 8 out channels ----
#pragma unroll
    for (int p = 0; p < 4; ++p) {
        const int o0 = ohalf*8 + 2*p;
        float* op0 = out + ((size_t)(b*CCH + o0    )) * PLANE;
        float* op1 = out + ((size_t)(b*CCH + o0 + 1)) * PLANE;
#pragma unroll
        for (int r = 0; r < 8; ++r) {
            const int gy = by + rowgrp*8 + r;
            const unsigned int lo = (unsigned int)(acc[r][p] & 0xffffffffull);
            const unsigned int hi = (unsigned int)(acc[r][p] >> 32);
            op0[gy*HW + bx + col] = __uint_as_float(lo);
            op1[gy*HW + bx + col] = __uint_as_float(hi);
        }
    }
}

// ---------------------------------------------------------------------------
// Per-(b,c) mean / rstd over one 512x512 plane. 64 blocks, deterministic.
// ---------------------------------------------------------------------------
__global__ void stats_kernel(const float* __restrict__ z,
                             float* __restrict__ mean,
                             float* __restrict__ rstd)
{
    __shared__ float sh_s[1024];
    __shared__ float sh_q[1024];
    const int bc = blockIdx.x;
    const float4* p = reinterpret_cast<const float4*>(z + (size_t)bc * PLANE);
    float s = 0.0f, q = 0.0f;
    for (int i = threadIdx.x; i < PLANE/4; i += 1024) {
        const float4 v = p[i];
        s += v.x + v.y + v.z + v.w;
        q += v.x*v.x + v.y*v.y + v.z*v.z + v.w*v.w;
    }
    sh_s[threadIdx.x] = s;
    sh_q[threadIdx.x] = q;
    __syncthreads();
    for (int off = 512; off > 0; off >>= 1) {
        if (threadIdx.x < off) {
            sh_s[threadIdx.x] += sh_s[threadIdx.x + off];
            sh_q[threadIdx.x] += sh_q[threadIdx.x + off];
        }
        __syncthreads();
    }
    if (threadIdx.x == 0) {
        const float m   = sh_s[0] * (1.0f / PLANE);
        const float var = sh_q[0] * (1.0f / PLANE) - m*m;
        mean[bc] = m;
        rstd[bc] = rsqrtf(var + 1e-5f);
    }
}

// ---------------------------------------------------------------------------
// out = sigmoid(prelu((z - mean)*rstd, alpha)), vectorized float4
// ---------------------------------------------------------------------------
__global__ void finalize_kernel(const float* __restrict__ z,
                                const float* __restrict__ mean,
                                const float* __restrict__ rstd,
                                const float* __restrict__ alpha_p,
                                float* __restrict__ out)
{
    const size_t i4 = (size_t)blockIdx.x * blockDim.x + threadIdx.x;
    if (i4 >= TOTAL/4) return;
    const int bc = (int)(i4 >> 16);   // (i4*4) / PLANE
    const float alpha = alpha_p[0];
    const float m = mean[bc], rs = rstd[bc];
    float4 v = reinterpret_cast<const float4*>(z)[i4];
    float* vp = &v.x;
#pragma unroll
    for (int k = 0; k < 4; ++k) {
        float t = (vp[k] - m) * rs;
        t = (t < 0.0f) ? alpha * t : t;
        vp[k] = 1.0f / (1.0f + __expf(-t));
    }
    reinterpret_cast<float4*>(out)[i4] = v;
}

// ---------------------------------------------------------------------------
extern "C" void kernel_launch(void* const* d_in, const int* in_sizes, int n_in,
                              void* d_out, int out_size)
{
    const float* x   = (const float*)d_in[0];
    const float* bw1 = (const float*)d_in[1];
    const float* sw1 = (const float*)d_in[2];
    const float* a1  = (const float*)d_in[3];
    const float* bw2 = (const float*)d_in[4];
    const float* sw2 = (const float*)d_in[5];
    const float* a2  = (const float*)d_in[6];
    float* out = (float*)d_out;

    float *z1, *z2, *m1, *r1, *m2, *r2;
    cudaGetSymbolAddress((void**)&z1, g_z1);
    cudaGetSymbolAddress((void**)&z2, g_z2);
    cudaGetSymbolAddress((void**)&m1, g_m1);
    cudaGetSymbolAddress((void**)&r1, g_r1);
    cudaGetSymbolAddress((void**)&m2, g_m2);
    cudaGetSymbolAddress((void**)&r2, g_r2);

    cudaFuncSetAttribute(conv_kan_kernel<false>,
                         cudaFuncAttributeMaxDynamicSharedMemorySize, SMEM_BYTES);
    cudaFuncSetAttribute(conv_kan_kernel<true>,
                         cudaFuncAttributeMaxDynamicSharedMemorySize, SMEM_BYTES);

    const dim3 grid(HW/TILE, HW/TILE, NB);   // 16 x 16 x 4

    // Layer 1
    conv_kan_kernel<false><<<grid, 256, SMEM_BYTES>>>(
        x, bw1, sw1, nullptr, nullptr, nullptr, z1);
    stats_kernel<<<NB*CCH, 1024>>>(z1, m1, r1);

    // Layer 2 (norm+prelu of layer-1 output fused into its input load)
    conv_kan_kernel<true><<<grid, 256, SMEM_BYTES>>>(
        z1, bw2, sw2, m1, r1, a1, z2);
    stats_kernel<<<NB*CCH, 1024>>>(z2, m2, r2);

    // Final norm + prelu + sigmoid
    finalize_kernel<<<(TOTAL/4 + 255)/256, 256>>>(z2, m2, r2, a2, out);
}

// round 5
// speedup vs baseline: 1.5674x; 1.5674x over previous
#include <cuda_runtime.h>
#include <cstdint>

// ---------------------------------------------------------------------------
// ConvKanModel via warp-level tf32 mma.sync implicit GEMM (sm_103 base target;
// tcgen05 is unavailable: harness compiles for sm_103, not sm_103a).
// Per layer, per 32x32 tile: D[1024px][16out] += A[px][K]·B[K][16] per input
// channel, K = tap*12 + j (9 taps x (silu + 11 cubic B-spline bases)), padded
// to 112. A staged in smem as 12 tf32 feature planes (stride 1160 words for
// conflict-free fragment loads); B staged per channel as [j][tap][16].
// ---------------------------------------------------------------------------

#define NB      4
#define CCH     16
#define HW      512
#define PLANE   (HW*HW)
#define TOTAL   (NB*CCH*PLANE)

#define TILE    32
#define HALO    34
#define HALO2   (HALO*HALO)       // 1156
#define PL      1160              // padded feature-plane stride (words)
#define NWW     1728              // weights per channel (12*9*16)
// smem word layout: s_act[12*PL] | s_w[NWW+16] | s_kf[112 uint2]
#define W_ACT   0
#define W_W     (12*PL)               // 13920
#define W_KF    (W_W + NWW + 16)      // 15664 (byte 62656, 8B aligned)
#define SMEM_WORDS (W_KF + 224)
#define SMEM_BYTES (SMEM_WORDS*4)     // 63552

__device__ float g_z1[TOTAL];
__device__ float g_z2[TOTAL];
__device__ float g_m1[64], g_r1[64], g_m2[64], g_r2[64];

__device__ __forceinline__ uint32_t f2tf32(float x) {
    uint32_t u;
    asm("cvt.rna.tf32.f32 %0, %1;" : "=r"(u) : "f"(x));
    return u;
}

__device__ __forceinline__ void mma_tf(float& c0, float& c1, float& c2, float& c3,
                                       uint32_t a0, uint32_t a1, uint32_t a2, uint32_t a3,
                                       uint32_t b0, uint32_t b1) {
    asm volatile("mma.sync.aligned.m16n8k8.row.col.f32.tf32.tf32.f32 "
                 "{%0,%1,%2,%3}, {%4,%5,%6,%7}, {%8,%9}, {%0,%1,%2,%3};"
                 : "+f"(c0), "+f"(c1), "+f"(c2), "+f"(c3)
                 : "r"(a0), "r"(a1), "r"(a2), "r"(a3), "r"(b0), "r"(b1));
}

// ---------------------------------------------------------------------------
// Fused KAN conv. Block: 512 threads (16 warps), 32x32 tile, 16 out channels.
// Warp w owns rows 2w..2w+1: 4 m16 tiles (row, half). 32 acc f32 per thread.
// ---------------------------------------------------------------------------
template<bool NORM>
__global__ __launch_bounds__(512, 1)
void conv_kan_mma(const float* __restrict__ in,
                  const float* __restrict__ base_w,    // [16][16][3][3]
                  const float* __restrict__ spline_w,  // [16][176][3][3]
                  const float* __restrict__ mean,
                  const float* __restrict__ rstd,
                  const float* __restrict__ alpha_p,
                  float* __restrict__ out)
{
    extern __shared__ uint32_t sm[];
    uint32_t* s_act = sm + W_ACT;
    uint32_t* s_w   = sm + W_W;
    uint2*    s_kf  = reinterpret_cast<uint2*>(sm + W_KF);

    const int tid  = threadIdx.x;
    const int lane = tid & 31;
    const int wy   = tid >> 5;          // warp id 0..15 -> rows 2wy, 2wy+1
    const int gid  = lane >> 2;         // fragment group id 0..7
    const int tig  = lane & 3;          // thread-in-group 0..3
    const int bx   = blockIdx.x * TILE;
    const int by   = blockIdx.y * TILE;
    const int b    = blockIdx.z;

    // ---- one-time init: k-offset table (word offsets) + zero B slot ----
    for (int k = tid; k < 112; k += 512) {
        uint2 e;
        if (k < 108) {
            const int tap = k / 12, j = k - tap * 12;
            const int ky = tap / 3, kx = tap - ky * 3;
            e.x = (uint32_t)(j * PL + ky * HALO + kx);   // A offset (words)
            e.y = (uint32_t)((j * 9 + tap) * 16);        // B offset (words)
        } else {
            e.x = 0u;                                    // A: any valid addr
            e.y = (uint32_t)(NWW);                       // B: zero slot
        }
        s_kf[k] = e;
    }
    if (tid < 16) s_w[NWW + tid] = 0u;                   // zero B slot

    // per-thread m-tile bases (words): (row*34 + half*16)
    uint32_t mb[4];
#pragma unroll
    for (int mt = 0; mt < 4; ++mt)
        mb[mt] = (uint32_t)((wy*2 + (mt >> 1)) * HALO + (mt & 1) * 16);

    const float alpha = NORM ? alpha_p[0] : 0.0f;

    float acc[4][8];
#pragma unroll
    for (int mt = 0; mt < 4; ++mt)
#pragma unroll
        for (int q = 0; q < 8; ++q) acc[mt][q] = 0.0f;

    for (int c = 0; c < CCH; ++c) {
        __syncthreads();   // protect previous iteration's reads (covers init too)

        // ---- stage activation features (tf32) for input channel c ----
        const float* inp = in + ((size_t)(b*CCH + c)) * PLANE;
        float mu = 0.0f, rs = 0.0f;
        if (NORM) { mu = mean[b*CCH + c]; rs = rstd[b*CCH + c]; }

        for (int idx = tid; idx < HALO2; idx += 512) {
            const int iy = idx / HALO;
            const int ix = idx - iy * HALO;
            const int gy = by + iy - 1;
            const int gx = bx + ix - 1;

            float f[12];
#pragma unroll
            for (int j = 0; j < 12; ++j) f[j] = 0.0f;
            if (gy >= 0 && gy < HW && gx >= 0 && gx < HW) {
                float x = inp[gy*HW + gx];
                if (NORM) {
                    x = (x - mu) * rs;
                    x = (x < 0.0f) ? alpha * x : x;      // prelu
                }
                f[0] = x / (1.0f + __expf(-x));          // silu
                const float u  = (x + 1.75f) * 4.0f;
                const float cf = floorf(u);
                const int   ci = (int)cf;
                if (ci >= 0 && ci < 14) {
                    const float t = u - cf, m1t = 1.0f - t, t2 = t*t, t3 = t2*t;
                    const float w0 = m1t*m1t*m1t*(1.0f/6.0f);
                    const float w1 = (3.0f*t3 - 6.0f*t2 + 4.0f)*(1.0f/6.0f);
                    const float w2 = (-3.0f*t3 + 3.0f*t2 + 3.0f*t + 1.0f)*(1.0f/6.0f);
                    const float w3 = t3*(1.0f/6.0f);
                    if (ci >= 3)              f[ci-2] = w0;   // basis ci-3 -> slot j
                    if (ci >= 2 && ci <= 12)  f[ci-1] = w1;
                    if (ci >= 1 && ci <= 11)  f[ci  ] = w2;
                    if (ci <= 10)             f[ci+1] = w3;
                }
            }
#pragma unroll
            for (int j = 0; j < 12; ++j)
                s_act[j*PL + idx] = f2tf32(f[j]);
        }

        // ---- stage weights (tf32): s_w[(j*9 + tap)*16 + o] ----
        for (int idx = tid; idx < NWW; idx += 512) {
            const int o    = idx & 15;
            const int rest = idx >> 4;        // 0..107
            const int kx   = rest % 3;
            const int ky   = (rest / 3) % 3;
            const int j    = rest / 9;
            float w;
            if (j == 0) w = base_w[((o*CCH + c)*3 + ky)*3 + kx];
            else        w = spline_w[((o*(CCH*11) + c*11 + (j-1))*3 + ky)*3 + kx];
            s_w[(j*9 + (ky*3 + kx))*16 + o] = f2tf32(w);
        }
        __syncthreads();

        // ---- 14 k8 chunks x 4 m-tiles x 2 n-tiles of mma ----
#pragma unroll
        for (int kc = 0; kc < 14; ++kc) {
            const uint2 k0 = s_kf[kc*8 + tig];
            const uint2 k1 = s_kf[kc*8 + tig + 4];
            const uint32_t b00 = s_w[k0.y + gid];        // n-tile 0
            const uint32_t b10 = s_w[k1.y + gid];
            const uint32_t b01 = s_w[k0.y + gid + 8];    // n-tile 1
            const uint32_t b11 = s_w[k1.y + gid + 8];
#pragma unroll
            for (int mt = 0; mt < 4; ++mt) {
                const uint32_t a0 = s_act[k0.x + mb[mt] + gid];
                const uint32_t a1 = s_act[k0.x + mb[mt] + gid + 8];
                const uint32_t a2 = s_act[k1.x + mb[mt] + gid];
                const uint32_t a3 = s_act[k1.x + mb[mt] + gid + 8];
                mma_tf(acc[mt][0], acc[mt][1], acc[mt][2], acc[mt][3],
                       a0, a1, a2, a3, b00, b10);
                mma_tf(acc[mt][4], acc[mt][5], acc[mt][6], acc[mt][7],
                       a0, a1, a2, a3, b01, b11);
            }
        }
    }

    // ---- epilogue: D fragment -> gmem ----
#pragma unroll
    for (int mt = 0; mt < 4; ++mt) {
        const int gy  = by + wy*2 + (mt >> 1);
        const int gxb = bx + (mt & 1)*16;
        const size_t rowoff = (size_t)gy * HW + gxb;
#pragma unroll
        for (int nt = 0; nt < 2; ++nt) {
            const int o0 = nt*8 + tig*2;
            float* p0 = out + (((size_t)(b*CCH + o0    )) << 18) + rowoff;
            float* p1 = out + (((size_t)(b*CCH + o0 + 1)) << 18) + rowoff;
            p0[gid    ] = acc[mt][nt*4 + 0];
            p1[gid    ] = acc[mt][nt*4 + 1];
            p0[gid + 8] = acc[mt][nt*4 + 2];
            p1[gid + 8] = acc[mt][nt*4 + 3];
        }
    }
}

// ---------------------------------------------------------------------------
__global__ void stats_kernel(const float* __restrict__ z,
                             float* __restrict__ mean, float* __restrict__ rstd)
{
    __shared__ float sh_s[1024], sh_q[1024];
    const int bc = blockIdx.x;
    const float4* p = reinterpret_cast<const float4*>(z + (size_t)bc * PLANE);
    float s = 0.0f, q = 0.0f;
    for (int i = threadIdx.x; i < PLANE/4; i += 1024) {
        const float4 v = p[i];
        s += v.x + v.y + v.z + v.w;
        q += v.x*v.x + v.y*v.y + v.z*v.z + v.w*v.w;
    }
    sh_s[threadIdx.x] = s; sh_q[threadIdx.x] = q;
    __syncthreads();
    for (int off = 512; off > 0; off >>= 1) {
        if (threadIdx.x < off) {
            sh_s[threadIdx.x] += sh_s[threadIdx.x + off];
            sh_q[threadIdx.x] += sh_q[threadIdx.x + off];
        }
        __syncthreads();
    }
    if (threadIdx.x == 0) {
        const float m = sh_s[0] * (1.0f/PLANE);
        const float v = sh_q[0] * (1.0f/PLANE) - m*m;
        mean[bc] = m; rstd[bc] = rsqrtf(v + 1e-5f);
    }
}

__global__ void finalize_kernel(const float* __restrict__ z,
                                const float* __restrict__ mean,
                                const float* __restrict__ rstd,
                                const float* __restrict__ alpha_p,
                                float* __restrict__ out)
{
    const size_t i4 = (size_t)blockIdx.x * blockDim.x + threadIdx.x;
    if (i4 >= TOTAL/4) return;
    const int bc = (int)(i4 >> 16);
    const float alpha = alpha_p[0], m = mean[bc], rs = rstd[bc];
    float4 v = reinterpret_cast<const float4*>(z)[i4];
    float* vp = &v.x;
#pragma unroll
    for (int k = 0; k < 4; ++k) {
        float t = (vp[k] - m) * rs;
        t = (t < 0.0f) ? alpha * t : t;
        vp[k] = 1.0f / (1.0f + __expf(-t));
    }
    reinterpret_cast<float4*>(out)[i4] = v;
}

// ---------------------------------------------------------------------------
extern "C" void kernel_launch(void* const* d_in, const int* in_sizes, int n_in,
                              void* d_out, int out_size)
{
    const float* x   = (const float*)d_in[0];
    const float* bw1 = (const float*)d_in[1];
    const float* sw1 = (const float*)d_in[2];
    const float* a1  = (const float*)d_in[3];
    const float* bw2 = (const float*)d_in[4];
    const float* sw2 = (const float*)d_in[5];
    const float* a2  = (const float*)d_in[6];
    float* out = (float*)d_out;

    float *z1, *z2, *m1, *r1, *m2, *r2;
    cudaGetSymbolAddress((void**)&z1, g_z1);
    cudaGetSymbolAddress((void**)&z2, g_z2);
    cudaGetSymbolAddress((void**)&m1, g_m1);
    cudaGetSymbolAddress((void**)&r1, g_r1);
    cudaGetSymbolAddress((void**)&m2, g_m2);
    cudaGetSymbolAddress((void**)&r2, g_r2);

    cudaFuncSetAttribute(conv_kan_mma<false>,
                         cudaFuncAttributeMaxDynamicSharedMemorySize, SMEM_BYTES);
    cudaFuncSetAttribute(conv_kan_mma<true>,
                         cudaFuncAttributeMaxDynamicSharedMemorySize, SMEM_BYTES);

    const dim3 grid(HW/TILE, HW/TILE, NB);   // 16 x 16 x 4

    conv_kan_mma<false><<<grid, 512, SMEM_BYTES>>>(
        x, bw1, sw1, nullptr, nullptr, nullptr, z1);
    stats_kernel<<<NB*CCH, 1024>>>(z1, m1, r1);

    conv_kan_mma<true><<<grid, 512, SMEM_BYTES>>>(
        z1, bw2, sw2, m1, r1, a1, z2);
    stats_kernel<<<NB*CCH, 1024>>>(z2, m2, r2);

    finalize_kernel<<<(TOTAL/4 + 255)/256, 256>>>(z2, m2, r2, a2, out);
}